// round 4
// baseline (speedup 1.0000x reference)
#include <cuda_runtime.h>

#define N_PTS 65536
#define N_NODES 4096
#define KSEL 20
#define IN_STRIDE 35
#define CAND_CAP 24
#define NBINS 4096

__device__ float4 g_nodes4[N_NODES];      // (vx, vy, vz, |v|^2)
__device__ float4 g_rec[N_NODES * 4];     // R[0..8], g+t, g
__device__ int    g_binCount[NBINS];
__device__ int    g_binCursor[NBINS];
__device__ int    g_cellArr[N_PTS];
__device__ int    g_perm[N_PTS];

__global__ void prep_kernel(const float* __restrict__ vd, const float* __restrict__ R,
                            const float* __restrict__ g, const float* __restrict__ t) {
    int j = blockIdx.x * blockDim.x + threadIdx.x;
    if (j >= N_NODES) return;
    float vx = vd[j*3+0], vy = vd[j*3+1], vz = vd[j*3+2];
    g_nodes4[j] = make_float4(vx, vy, vz, fmaf(vx,vx,fmaf(vy,vy,vz*vz)));
    const float* Rj = R + j*9;
    float g0 = g[j*3+0], g1 = g[j*3+1], g2 = g[j*3+2];
    float gt0 = g0 + t[j*3+0], gt1 = g1 + t[j*3+1], gt2 = g2 + t[j*3+2];
    g_rec[j*4+0] = make_float4(Rj[0], Rj[1], Rj[2], Rj[3]);
    g_rec[j*4+1] = make_float4(Rj[4], Rj[5], Rj[6], Rj[7]);
    g_rec[j*4+2] = make_float4(Rj[8], gt0, gt1, gt2);
    g_rec[j*4+3] = make_float4(g0, g1, g2, 0.0f);
}

__device__ __forceinline__ unsigned expand3(unsigned v) {
    return (v & 1u) | ((v & 2u) << 2) | ((v & 4u) << 4) | ((v & 8u) << 6);
}
__device__ __forceinline__ int quant4(float x) {
    int q = (int)((x + 3.0f) * (16.0f / 6.0f));
    return q < 0 ? 0 : (q > 15 ? 15 : q);
}

__global__ void zero_bins_kernel() {
    int i = blockIdx.x * blockDim.x + threadIdx.x;
    if (i < NBINS) g_binCount[i] = 0;
}

__global__ void bin_count_kernel(const float* __restrict__ inputs) {
    int pt = blockIdx.x * blockDim.x + threadIdx.x;
    if (pt >= N_PTS) return;
    const float* pr = inputs + (long)pt * IN_STRIDE;
    unsigned code = expand3(quant4(pr[0])) | (expand3(quant4(pr[1])) << 1)
                  | (expand3(quant4(pr[2])) << 2);
    g_cellArr[pt] = (int)code;
    atomicAdd(&g_binCount[code], 1);
}

__global__ void scan_bins_kernel() {
    __shared__ int ssum[1024];
    int tid = threadIdx.x;
    int base = tid * 4;
    int c0 = g_binCount[base], c1 = g_binCount[base+1];
    int c2 = g_binCount[base+2], c3 = g_binCount[base+3];
    ssum[tid] = c0 + c1 + c2 + c3;
    __syncthreads();
    for (int off = 1; off < 1024; off <<= 1) {
        int v = ssum[tid];
        int add = (tid >= off) ? ssum[tid - off] : 0;
        __syncthreads();
        ssum[tid] = v + add;
        __syncthreads();
    }
    int excl = (tid > 0) ? ssum[tid - 1] : 0;
    g_binCursor[base]   = excl;
    g_binCursor[base+1] = excl + c0;
    g_binCursor[base+2] = excl + c0 + c1;
    g_binCursor[base+3] = excl + c0 + c1 + c2;
}

__global__ void scatter_kernel() {
    int pt = blockIdx.x * blockDim.x + threadIdx.x;
    if (pt >= N_PTS) return;
    int pos = atomicAdd(&g_binCursor[g_cellArr[pt]], 1);
    g_perm[pos] = pt;
}

__global__ void __launch_bounds__(128) dg_kernel(const float* __restrict__ inputs,
                                                 float* __restrict__ out) {
    __shared__ int   s_cand[N_NODES];   // 16 KB, cannot overflow
    __shared__ float s_rx[4], s_ry[4], s_rz[4], s_rm[4];
    __shared__ int   s_wcnt[4];

    const int tid  = threadIdx.x;
    const int lane = tid & 31;
    const int wid  = tid >> 5;

    const int pt = g_perm[blockIdx.x * 128 + tid];
    const float* pr = inputs + (long)pt * IN_STRIDE;
    const float px = pr[0], py = pr[1], pz = pr[2];
    const float pp = fmaf(px, px, fmaf(py, py, pz * pz));
    const float qa = -2.0f * px, qb = -2.0f * py, qc = -2.0f * pz;

    // ---- Block centroid ----
    float sx = px, sy = py, sz = pz;
    #pragma unroll
    for (int o = 16; o; o >>= 1) {
        sx += __shfl_xor_sync(0xffffffffu, sx, o);
        sy += __shfl_xor_sync(0xffffffffu, sy, o);
        sz += __shfl_xor_sync(0xffffffffu, sz, o);
    }
    if (lane == 0) { s_rx[wid] = sx; s_ry[wid] = sy; s_rz[wid] = sz; }
    __syncthreads();
    const float cx = (s_rx[0]+s_rx[1]+s_rx[2]+s_rx[3]) * (1.0f/128.0f);
    const float cy = (s_ry[0]+s_ry[1]+s_ry[2]+s_ry[3]) * (1.0f/128.0f);
    const float cz = (s_rz[0]+s_rz[1]+s_rz[2]+s_rz[3]) * (1.0f/128.0f);

    // ---- Block radius ----
    float dxp = px - cx, dyp = py - cy, dzp = pz - cz;
    float r2 = fmaf(dxp, dxp, fmaf(dyp, dyp, dzp * dzp));
    #pragma unroll
    for (int o = 16; o; o >>= 1)
        r2 = fmaxf(r2, __shfl_xor_sync(0xffffffffu, r2, o));
    if (lane == 0) s_rm[wid] = r2;
    __syncthreads();
    const float rblk = sqrtf(fmaxf(fmaxf(s_rm[0], s_rm[1]), fmaxf(s_rm[2], s_rm[3])));

    // ---- Prefilter: node distances to centroid (32 nodes/thread, in regs) ----
    float d2i[32];
    #pragma unroll
    for (int i = 0; i < 32; i++) {
        float4 v = __ldg(&g_nodes4[tid + 128 * i]);
        float dx = v.x - cx, dy = v.y - cy, dz = v.z - cz;
        d2i[i] = fmaf(dx, dx, fmaf(dy, dy, dz * dz));
    }

    // ---- Binary search: upper bound hi on D20c^2 (count(d2<=hi) >= 20) ----
    float lo = 0.0f, hi = 512.0f;
    for (int it = 0; it < 20; it++) {
        float mid = 0.5f * (lo + hi);
        int cnt = 0;
        #pragma unroll
        for (int i = 0; i < 32; i++) cnt += (d2i[i] <= mid) ? 1 : 0;
        #pragma unroll
        for (int o = 16; o; o >>= 1)
            cnt += __shfl_xor_sync(0xffffffffu, cnt, o);
        __syncthreads();
        if (lane == 0) s_wcnt[wid] = cnt;
        __syncthreads();
        int tot = s_wcnt[0] + s_wcnt[1] + s_wcnt[2] + s_wcnt[3];
        if (tot >= 20) hi = mid; else lo = mid;
    }
    const float thr = sqrtf(hi) + 2.0f * rblk + 2e-3f;
    const float thr2 = thr * thr;

    // ---- Deterministic compaction of candidate ids into shared ----
    unsigned m = 0;
    #pragma unroll
    for (int i = 0; i < 32; i++)
        m |= (d2i[i] <= thr2 ? 1u : 0u) << i;
    int myc = __popc(m);
    int incl = myc;
    #pragma unroll
    for (int o = 1; o < 32; o <<= 1) {
        int tv = __shfl_up_sync(0xffffffffu, incl, o);
        if (lane >= o) incl += tv;
    }
    __syncthreads();
    if (lane == 31) s_wcnt[wid] = incl;
    __syncthreads();
    int base = 0;
    #pragma unroll
    for (int wj = 0; wj < 4; wj++) if (wj < wid) base += s_wcnt[wj];
    const int C = s_wcnt[0] + s_wcnt[1] + s_wcnt[2] + s_wcnt[3];
    int pos = base + incl - myc;
    #pragma unroll
    for (int i = 0; i < 32; i++)
        if (m & (1u << i)) s_cand[pos++] = tid + 128 * i;
    __syncthreads();

    // ---- Pass 1: top-20 scores s = |v|^2 - 2 p.v over candidates ----
    float d[KSEL];
    #pragma unroll
    for (int k = 0; k < KSEL; k++) d[k] = 3.0e38f;

    #pragma unroll 4
    for (int jj = 0; jj < C; jj++) {
        float4 v = __ldg(&g_nodes4[s_cand[jj]]);
        float s = fmaf(qa, v.x, fmaf(qb, v.y, fmaf(qc, v.z, v.w)));
        if (__any_sync(0xffffffffu, s < d[KSEL-1])) {
            #pragma unroll
            for (int k = KSEL-1; k >= 1; --k)
                d[k] = fminf(d[k], fmaxf(d[k-1], s));
            d[0] = fminf(d[0], s);
        }
    }

    const float T = d[KSEL-1];
    const float dis0 = d[0] + pp;
    const float dismax = T + pp;
    const float rcpmax = 1.0f / dismax;

    // ---- Pass 2: collect ids with s <= T ----
    int   ids[CAND_CAP];
    float ss [CAND_CAP];
    int cnt = 0;
    #pragma unroll 4
    for (int jj = 0; jj < C; jj++) {
        int j = s_cand[jj];
        float4 v = __ldg(&g_nodes4[j]);
        float s = fmaf(qa, v.x, fmaf(qb, v.y, fmaf(qc, v.z, v.w)));
        if (s <= T && cnt < CAND_CAP) {
            ids[cnt] = j;
            ss[cnt]  = s;
            cnt++;
        }
    }

    // ---- Phase 3: gather node records, weight, blend ----
    float wsum = 0.0f, pb0 = 0.0f, pb1 = 0.0f, pb2 = 0.0f;
    float rb[9];
    #pragma unroll
    for (int i = 0; i < 9; i++) rb[i] = 0.0f;

    for (int k = 0; k < cnt; k++) {
        int j = ids[k];
        float dis = ss[k] + pp;
        float u = 1.0f - dis * rcpmax;
        float w = u * u;
        const float4* rec = g_rec + j * 4;
        float4 r0 = __ldg(rec + 0);
        float4 r1 = __ldg(rec + 1);
        float4 r2v = __ldg(rec + 2);
        float4 r3 = __ldg(rec + 3);
        float y0 = px - r2v.y, y1 = py - r2v.z, y2 = pz - r2v.w;
        float q0 = fmaf(r0.x, y0, fmaf(r0.w, y1, fmaf(r1.z, y2, r3.x)));
        float q1 = fmaf(r0.y, y0, fmaf(r1.x, y1, fmaf(r1.w, y2, r3.y)));
        float q2 = fmaf(r0.z, y0, fmaf(r1.y, y1, fmaf(r2v.x, y2, r3.z)));
        wsum += w;
        pb0 = fmaf(w, q0, pb0);
        pb1 = fmaf(w, q1, pb1);
        pb2 = fmaf(w, q2, pb2);
        rb[0] = fmaf(w, r0.x, rb[0]);
        rb[1] = fmaf(w, r0.w, rb[1]);
        rb[2] = fmaf(w, r1.z, rb[2]);
        rb[3] = fmaf(w, r0.y, rb[3]);
        rb[4] = fmaf(w, r1.x, rb[4]);
        rb[5] = fmaf(w, r1.w, rb[5]);
        rb[6] = fmaf(w, r0.z, rb[6]);
        rb[7] = fmaf(w, r1.y, rb[7]);
        rb[8] = fmaf(w, r2v.x, rb[8]);
    }

    const float inv = 1.0f / wsum;
    float o0 = (dis0 > 0.00021f) ? 1000000000.0f : pb0 * inv;
    float* op = out + (long)pt * 3;
    op[0] = o0;
    op[1] = pb1 * inv;
    op[2] = pb2 * inv;
    float* orr = out + (long)N_PTS * 3 + (long)pt * 9;
    #pragma unroll
    for (int i = 0; i < 9; i++) orr[i] = rb[i] * inv;
}

extern "C" void kernel_launch(void* const* d_in, const int* in_sizes, int n_in,
                              void* d_out, int out_size) {
    const float* inputs = (const float*)d_in[0];
    const float* vd     = (const float*)d_in[1];
    const float* R      = (const float*)d_in[2];
    const float* g      = (const float*)d_in[3];
    const float* t      = (const float*)d_in[4];
    float* out = (float*)d_out;

    prep_kernel<<<(N_NODES + 255) / 256, 256>>>(vd, R, g, t);
    zero_bins_kernel<<<NBINS / 256, 256>>>();
    bin_count_kernel<<<N_PTS / 256, 256>>>(inputs);
    scan_bins_kernel<<<1, 1024>>>();
    scatter_kernel<<<N_PTS / 256, 256>>>();
    dg_kernel<<<N_PTS / 128, 128>>>(inputs, out);
}

// round 5
// speedup vs baseline: 1.1491x; 1.1491x over previous
#include <cuda_runtime.h>

#define N_PTS 65536
#define N_NODES 4096
#define KSEL 20
#define IN_STRIDE 35
#define CHUNK_N 2048
#define CAND_CAP 24
#define CAP_LOG 160
#define NBINS 32768

__device__ float4 g_nodes4[N_NODES];      // (vx, vy, vz, |v|^2)
__device__ float4 g_rec[N_NODES * 4];     // R[0..8], g+t, g
__device__ int    g_binCount[NBINS];
__device__ int    g_binCursor[NBINS];
__device__ int    g_cellArr[N_PTS];
__device__ int    g_perm[N_PTS];

__global__ void prep_kernel(const float* __restrict__ vd, const float* __restrict__ R,
                            const float* __restrict__ g, const float* __restrict__ t) {
    int j = blockIdx.x * blockDim.x + threadIdx.x;
    if (j >= N_NODES) return;
    float vx = vd[j*3+0], vy = vd[j*3+1], vz = vd[j*3+2];
    g_nodes4[j] = make_float4(vx, vy, vz, fmaf(vx,vx,fmaf(vy,vy,vz*vz)));
    const float* Rj = R + j*9;
    float g0 = g[j*3+0], g1 = g[j*3+1], g2 = g[j*3+2];
    float gt0 = g0 + t[j*3+0], gt1 = g1 + t[j*3+1], gt2 = g2 + t[j*3+2];
    g_rec[j*4+0] = make_float4(Rj[0], Rj[1], Rj[2], Rj[3]);
    g_rec[j*4+1] = make_float4(Rj[4], Rj[5], Rj[6], Rj[7]);
    g_rec[j*4+2] = make_float4(Rj[8], gt0, gt1, gt2);
    g_rec[j*4+3] = make_float4(g0, g1, g2, 0.0f);
}

__device__ __forceinline__ unsigned expand5(unsigned v) {
    return (v & 1u) | ((v & 2u) << 2) | ((v & 4u) << 4) | ((v & 8u) << 6) | ((v & 16u) << 8);
}
__device__ __forceinline__ int quant5(float x) {
    int q = (int)((x + 3.0f) * (32.0f / 6.0f));
    return q < 0 ? 0 : (q > 31 ? 31 : q);
}

__global__ void zero_bins_kernel() {
    int i = blockIdx.x * blockDim.x + threadIdx.x;
    if (i < NBINS) g_binCount[i] = 0;
}

__global__ void bin_count_kernel(const float* __restrict__ inputs) {
    int pt = blockIdx.x * blockDim.x + threadIdx.x;
    if (pt >= N_PTS) return;
    const float* pr = inputs + (long)pt * IN_STRIDE;
    unsigned code = expand5(quant5(pr[0])) | (expand5(quant5(pr[1])) << 1)
                  | (expand5(quant5(pr[2])) << 2);
    g_cellArr[pt] = (int)code;
    atomicAdd(&g_binCount[code], 1);
}

// One block, 1024 threads, 32 bins per thread.
__global__ void scan_bins_kernel() {
    __shared__ int ssum[1024];
    int tid = threadIdx.x;
    int base = tid * 32;
    int c[32];
    int tot = 0;
    #pragma unroll
    for (int i = 0; i < 32; i++) { c[i] = g_binCount[base + i]; tot += c[i]; }
    ssum[tid] = tot;
    __syncthreads();
    for (int off = 1; off < 1024; off <<= 1) {
        int v = ssum[tid];
        int add = (tid >= off) ? ssum[tid - off] : 0;
        __syncthreads();
        ssum[tid] = v + add;
        __syncthreads();
    }
    int run = (tid > 0) ? ssum[tid - 1] : 0;
    #pragma unroll
    for (int i = 0; i < 32; i++) { g_binCursor[base + i] = run; run += c[i]; }
}

__global__ void scatter_kernel() {
    int pt = blockIdx.x * blockDim.x + threadIdx.x;
    if (pt >= N_PTS) return;
    int pos = atomicAdd(&g_binCursor[g_cellArr[pt]], 1);
    g_perm[pos] = pt;
}

__device__ __forceinline__ unsigned long long pack_sj(float s, int j) {
    return ((unsigned long long)__float_as_uint(s) << 32) | (unsigned)j;
}

__global__ void __launch_bounds__(128) dg_kernel(const float* __restrict__ inputs,
                                                 float* __restrict__ out) {
    __shared__ float4 sn[CHUNK_N];   // 32 KB

    const int tid = threadIdx.x;
    const int pt = g_perm[blockIdx.x * 128 + tid];
    const float* pr = inputs + (long)pt * IN_STRIDE;
    const float px = pr[0], py = pr[1], pz = pr[2];
    const float pp = fmaf(px, px, fmaf(py, py, pz * pz));
    const float qa = -2.0f * px, qb = -2.0f * py, qc = -2.0f * pz;

    unsigned long long logbuf[CAP_LOG];   // local memory accept log
    int cnt = 0;

    // ---- Pass 1: top-20 smallest s = |v|^2 - 2 p.v, logging accepts ----
    float d[KSEL];
    #pragma unroll
    for (int k = 0; k < KSEL; k++) d[k] = 3.0e38f;

    for (int ch = 0; ch < N_NODES / CHUNK_N; ch++) {
        __syncthreads();
        #pragma unroll
        for (int i = tid; i < CHUNK_N; i += 128)
            sn[i] = g_nodes4[ch * CHUNK_N + i];
        __syncthreads();
        const int jbase = ch * CHUNK_N;
        #pragma unroll 2
        for (int j = 0; j < CHUNK_N; j += 2) {
            float4 v0 = sn[j];
            float4 v1 = sn[j + 1];
            float s0 = fmaf(qa, v0.x, fmaf(qb, v0.y, fmaf(qc, v0.z, v0.w)));
            float s1 = fmaf(qa, v1.x, fmaf(qb, v1.y, fmaf(qc, v1.z, v1.w)));
            if (__any_sync(0xffffffffu, fminf(s0, s1) < d[KSEL-1])) {
                if (__any_sync(0xffffffffu, s0 < d[KSEL-1])) {
                    if (s0 < d[KSEL-1]) {
                        logbuf[cnt < CAP_LOG ? cnt : CAP_LOG-1] = pack_sj(s0, jbase + j);
                        cnt++;
                    }
                    #pragma unroll
                    for (int k = KSEL-1; k >= 1; --k)
                        d[k] = fminf(d[k], fmaxf(d[k-1], s0));
                    d[0] = fminf(d[0], s0);
                }
                if (__any_sync(0xffffffffu, s1 < d[KSEL-1])) {
                    if (s1 < d[KSEL-1]) {
                        logbuf[cnt < CAP_LOG ? cnt : CAP_LOG-1] = pack_sj(s1, jbase + j + 1);
                        cnt++;
                    }
                    #pragma unroll
                    for (int k = KSEL-1; k >= 1; --k)
                        d[k] = fminf(d[k], fmaxf(d[k-1], s1));
                    d[0] = fminf(d[0], s1);
                }
            }
        }
    }

    const float T = d[KSEL-1];
    const float dis0 = d[0] + pp;
    const float dismax = T + pp;
    const float rcpmax = 1.0f / dismax;

    // ---- Collect final candidates (s <= T) from the log ----
    int   ids[CAND_CAP];
    float ssv[CAND_CAP];
    int c = 0;
    bool ovf = cnt > CAP_LOG;
    if (__any_sync(0xffffffffu, ovf)) {
        // rare fallback: full rescan from global (uniform broadcast reads)
        for (int j = 0; j < N_NODES; j++) {
            float4 v = __ldg(&g_nodes4[j]);
            float s = fmaf(qa, v.x, fmaf(qb, v.y, fmaf(qc, v.z, v.w)));
            if (s <= T && c < CAND_CAP) { ids[c] = j; ssv[c] = s; c++; }
        }
    } else {
        for (int k = 0; k < cnt; k++) {
            unsigned long long e = logbuf[k];
            float s = __uint_as_float((unsigned)(e >> 32));
            if (s <= T && c < CAND_CAP) {
                ids[c] = (int)(e & 0xffffffffu);
                ssv[c] = s;
                c++;
            }
        }
    }

    // ---- Phase 3: gather node records, weight, blend ----
    float wsum = 0.0f, pb0 = 0.0f, pb1 = 0.0f, pb2 = 0.0f;
    float rb[9];
    #pragma unroll
    for (int i = 0; i < 9; i++) rb[i] = 0.0f;

    for (int k = 0; k < c; k++) {
        int j = ids[k];
        float dis = ssv[k] + pp;
        float u = 1.0f - dis * rcpmax;
        float w = u * u;
        const float4* rec = g_rec + j * 4;
        float4 r0 = __ldg(rec + 0);
        float4 r1 = __ldg(rec + 1);
        float4 r2v = __ldg(rec + 2);
        float4 r3 = __ldg(rec + 3);
        float y0 = px - r2v.y, y1 = py - r2v.z, y2 = pz - r2v.w;
        float q0 = fmaf(r0.x, y0, fmaf(r0.w, y1, fmaf(r1.z, y2, r3.x)));
        float q1 = fmaf(r0.y, y0, fmaf(r1.x, y1, fmaf(r1.w, y2, r3.y)));
        float q2 = fmaf(r0.z, y0, fmaf(r1.y, y1, fmaf(r2v.x, y2, r3.z)));
        wsum += w;
        pb0 = fmaf(w, q0, pb0);
        pb1 = fmaf(w, q1, pb1);
        pb2 = fmaf(w, q2, pb2);
        rb[0] = fmaf(w, r0.x, rb[0]);
        rb[1] = fmaf(w, r0.w, rb[1]);
        rb[2] = fmaf(w, r1.z, rb[2]);
        rb[3] = fmaf(w, r0.y, rb[3]);
        rb[4] = fmaf(w, r1.x, rb[4]);
        rb[5] = fmaf(w, r1.w, rb[5]);
        rb[6] = fmaf(w, r0.z, rb[6]);
        rb[7] = fmaf(w, r1.y, rb[7]);
        rb[8] = fmaf(w, r2v.x, rb[8]);
    }

    const float inv = 1.0f / wsum;
    float o0 = (dis0 > 0.00021f) ? 1000000000.0f : pb0 * inv;
    float* op = out + (long)pt * 3;
    op[0] = o0;
    op[1] = pb1 * inv;
    op[2] = pb2 * inv;
    float* orr = out + (long)N_PTS * 3 + (long)pt * 9;
    #pragma unroll
    for (int i = 0; i < 9; i++) orr[i] = rb[i] * inv;
}

extern "C" void kernel_launch(void* const* d_in, const int* in_sizes, int n_in,
                              void* d_out, int out_size) {
    const float* inputs = (const float*)d_in[0];
    const float* vd     = (const float*)d_in[1];
    const float* R      = (const float*)d_in[2];
    const float* g      = (const float*)d_in[3];
    const float* t      = (const float*)d_in[4];
    float* out = (float*)d_out;

    prep_kernel<<<(N_NODES + 255) / 256, 256>>>(vd, R, g, t);
    zero_bins_kernel<<<NBINS / 256, 256>>>();
    bin_count_kernel<<<N_PTS / 256, 256>>>(inputs);
    scan_bins_kernel<<<1, 1024>>>();
    scatter_kernel<<<N_PTS / 256, 256>>>();
    dg_kernel<<<N_PTS / 128, 128>>>(inputs, out);
}